// round 1
// baseline (speedup 1.0000x reference)
#include <cuda_runtime.h>
#include <math.h>

#define BATCH 32
#define SEQ   1024
#define DIM   1024

#define BM 128
#define BN 128
#define BK 8
#define TM 8
#define TN 8
// 256 threads = (BM/TM) * (BN/TN)

// Scratch: similarity matrix E and softmax stats (sanctioned __device__ globals)
__device__ float g_E[(size_t)BATCH * SEQ * SEQ];          // 128 MB
__device__ float g_rowmax[BATCH * SEQ];
__device__ float g_rowinv[BATCH * SEQ];
__device__ float g_colmax[BATCH * SEQ];
__device__ float g_colinv[BATCH * SEQ];

// ---------------------------------------------------------------------------
// GEMM 1: E[b] = P[b] @ H[b]^T   (NT, both row-major K-contiguous)
// ---------------------------------------------------------------------------
__global__ __launch_bounds__(256, 2)
void gemm_e_kernel(const float* __restrict__ P, const float* __restrict__ H) {
    __shared__ float As[BK][BM];
    __shared__ float Bs[BK][BN];

    const int b  = blockIdx.z;
    const float* Pb = P + (size_t)b * SEQ * DIM;
    const float* Hb = H + (size_t)b * SEQ * DIM;
    float*       Eb = g_E + (size_t)b * SEQ * SEQ;

    const int m0 = blockIdx.y * BM;
    const int n0 = blockIdx.x * BN;
    const int tid = threadIdx.x;
    const int tx = tid & 15;          // 0..15 -> N
    const int ty = tid >> 4;          // 0..15 -> M
    const int lrow = tid >> 1;        // 0..127
    const int lk   = (tid & 1) * 4;   // 0 or 4

    float acc[TM][TN] = {};

    for (int k0 = 0; k0 < DIM; k0 += BK) {
        float4 va = *(const float4*)&Pb[(size_t)(m0 + lrow) * DIM + k0 + lk];
        float4 vb = *(const float4*)&Hb[(size_t)(n0 + lrow) * DIM + k0 + lk];
        As[lk + 0][lrow] = va.x; As[lk + 1][lrow] = va.y;
        As[lk + 2][lrow] = va.z; As[lk + 3][lrow] = va.w;
        Bs[lk + 0][lrow] = vb.x; Bs[lk + 1][lrow] = vb.y;
        Bs[lk + 2][lrow] = vb.z; Bs[lk + 3][lrow] = vb.w;
        __syncthreads();

        #pragma unroll
        for (int kk = 0; kk < BK; kk++) {
            float4 a0 = *(const float4*)&As[kk][ty * TM];
            float4 a1 = *(const float4*)&As[kk][ty * TM + 4];
            float4 b0 = *(const float4*)&Bs[kk][tx * TN];
            float4 b1 = *(const float4*)&Bs[kk][tx * TN + 4];
            const float ra[TM] = {a0.x, a0.y, a0.z, a0.w, a1.x, a1.y, a1.z, a1.w};
            const float rb[TN] = {b0.x, b0.y, b0.z, b0.w, b1.x, b1.y, b1.z, b1.w};
            #pragma unroll
            for (int i = 0; i < TM; i++)
                #pragma unroll
                for (int j = 0; j < TN; j++)
                    acc[i][j] += ra[i] * rb[j];
        }
        __syncthreads();
    }

    #pragma unroll
    for (int i = 0; i < TM; i++) {
        const int m = m0 + ty * TM + i;
        #pragma unroll
        for (int j = 0; j < TN; j += 4) {
            float4 v = make_float4(acc[i][j], acc[i][j + 1], acc[i][j + 2], acc[i][j + 3]);
            *(float4*)&Eb[(size_t)m * SEQ + n0 + tx * TN + j] = v;
        }
    }
}

// ---------------------------------------------------------------------------
// Row softmax stats (axis=2): one warp per row, online max/sum
// ---------------------------------------------------------------------------
__global__ __launch_bounds__(256)
void row_stats_kernel() {
    const int b    = blockIdx.y;
    const int warp = threadIdx.x >> 5;
    const int lane = threadIdx.x & 31;
    const int row  = blockIdx.x * 8 + warp;
    const float* Erow = g_E + (size_t)b * SEQ * SEQ + (size_t)row * SEQ;

    float m = -INFINITY, s = 0.f;
    #pragma unroll 4
    for (int j = lane; j < SEQ; j += 32) {
        float v = Erow[j];
        if (v > m) { s = s * __expf(m - v) + 1.f; m = v; }
        else       { s += __expf(v - m); }
    }
    #pragma unroll
    for (int off = 16; off; off >>= 1) {
        float om = __shfl_down_sync(0xffffffffu, m, off);
        float os = __shfl_down_sync(0xffffffffu, s, off);
        float nm = fmaxf(m, om);
        s = s * __expf(m - nm) + os * __expf(om - nm);
        m = nm;
    }
    if (lane == 0) {
        g_rowmax[b * SEQ + row] = m;
        g_rowinv[b * SEQ + row] = 1.f / s;
    }
}

// ---------------------------------------------------------------------------
// Column softmax stats (axis=1): one thread per column, coalesced over rows
// ---------------------------------------------------------------------------
__global__ __launch_bounds__(256)
void col_stats_kernel() {
    const int b = blockIdx.y;
    const int j = blockIdx.x * 256 + threadIdx.x;
    const float* Eb = g_E + (size_t)b * SEQ * SEQ;

    float m = -INFINITY, s = 0.f;
    #pragma unroll 4
    for (int i = 0; i < SEQ; i++) {
        float v = Eb[(size_t)i * SEQ + j];
        if (v > m) { s = s * __expf(m - v) + 1.f; m = v; }
        else       { s += __expf(v - m); }
    }
    g_colmax[b * SEQ + j] = m;
    g_colinv[b * SEQ + j] = 1.f / s;
}

// ---------------------------------------------------------------------------
// GEMM 2: attention_p[b] = rowsoftmax(E[b]) @ H[b]   (NN; weights fused in A load)
// ---------------------------------------------------------------------------
__global__ __launch_bounds__(256, 2)
void gemm_p_kernel(const float* __restrict__ H, float* __restrict__ outp) {
    __shared__ float As[BK][BM];
    __shared__ float Bs[BK][BN];

    const int b = blockIdx.z;
    const float* Eb = g_E + (size_t)b * SEQ * SEQ;
    const float* Hb = H + (size_t)b * SEQ * DIM;

    const int m0 = blockIdx.y * BM;
    const int n0 = blockIdx.x * BN;
    const int tid = threadIdx.x;
    const int tx = tid & 15, ty = tid >> 4;
    const int arow = tid >> 1;        // 0..127 (i)
    const int ak   = (tid & 1) * 4;   // 0 or 4 (j chunk)
    const int bk   = tid >> 5;        // 0..7
    const int bn   = (tid & 31) * 4;  // 0..124

    const float rm = g_rowmax[b * SEQ + m0 + arow];
    const float ri = g_rowinv[b * SEQ + m0 + arow];

    float acc[TM][TN] = {};

    for (int k0 = 0; k0 < SEQ; k0 += BK) {
        float4 va = *(const float4*)&Eb[(size_t)(m0 + arow) * SEQ + k0 + ak];
        As[ak + 0][arow] = __expf(va.x - rm) * ri;
        As[ak + 1][arow] = __expf(va.y - rm) * ri;
        As[ak + 2][arow] = __expf(va.z - rm) * ri;
        As[ak + 3][arow] = __expf(va.w - rm) * ri;
        float4 vb = *(const float4*)&Hb[(size_t)(k0 + bk) * DIM + n0 + bn];
        *(float4*)&Bs[bk][bn] = vb;
        __syncthreads();

        #pragma unroll
        for (int kk = 0; kk < BK; kk++) {
            float4 a0 = *(const float4*)&As[kk][ty * TM];
            float4 a1 = *(const float4*)&As[kk][ty * TM + 4];
            float4 b0 = *(const float4*)&Bs[kk][tx * TN];
            float4 b1 = *(const float4*)&Bs[kk][tx * TN + 4];
            const float ra[TM] = {a0.x, a0.y, a0.z, a0.w, a1.x, a1.y, a1.z, a1.w};
            const float rb[TN] = {b0.x, b0.y, b0.z, b0.w, b1.x, b1.y, b1.z, b1.w};
            #pragma unroll
            for (int i = 0; i < TM; i++)
                #pragma unroll
                for (int j = 0; j < TN; j++)
                    acc[i][j] += ra[i] * rb[j];
        }
        __syncthreads();
    }

    #pragma unroll
    for (int i = 0; i < TM; i++) {
        const int m = m0 + ty * TM + i;
        #pragma unroll
        for (int j = 0; j < TN; j += 4) {
            float4 v = make_float4(acc[i][j], acc[i][j + 1], acc[i][j + 2], acc[i][j + 3]);
            *(float4*)&outp[((size_t)b * SEQ + m) * DIM + n0 + tx * TN + j] = v;
        }
    }
}

// ---------------------------------------------------------------------------
// GEMM 3: attention_h[b,j,:] = sum_i colsoftmax(E)[i,j] * P[b,i,:]
// A' = colweighted(E)^T  (M=j, K=i) — E tiles load naturally K-major
// ---------------------------------------------------------------------------
__global__ __launch_bounds__(256, 2)
void gemm_h_kernel(const float* __restrict__ P, float* __restrict__ outh) {
    __shared__ float As[BK][BM];
    __shared__ float Bs[BK][BN];
    __shared__ float cm[BM];
    __shared__ float ci[BM];

    const int b = blockIdx.z;
    const float* Eb = g_E + (size_t)b * SEQ * SEQ;
    const float* Pb = P + (size_t)b * SEQ * DIM;

    const int m0 = blockIdx.y * BM;   // j-range
    const int n0 = blockIdx.x * BN;   // d-range
    const int tid = threadIdx.x;
    const int tx = tid & 15, ty = tid >> 4;

    if (tid < BM) {
        cm[tid] = g_colmax[b * SEQ + m0 + tid];
        ci[tid] = g_colinv[b * SEQ + m0 + tid];
    }
    __syncthreads();

    const int ak = tid >> 5;          // 0..7  (i chunk)
    const int am = (tid & 31) * 4;    // 0..124 (j)
    const int bk = tid >> 5;
    const int bn = (tid & 31) * 4;

    float acc[TM][TN] = {};

    for (int k0 = 0; k0 < SEQ; k0 += BK) {
        float4 ve = *(const float4*)&Eb[(size_t)(k0 + ak) * SEQ + m0 + am];
        As[ak][am + 0] = __expf(ve.x - cm[am + 0]) * ci[am + 0];
        As[ak][am + 1] = __expf(ve.y - cm[am + 1]) * ci[am + 1];
        As[ak][am + 2] = __expf(ve.z - cm[am + 2]) * ci[am + 2];
        As[ak][am + 3] = __expf(ve.w - cm[am + 3]) * ci[am + 3];
        float4 vb = *(const float4*)&Pb[(size_t)(k0 + bk) * DIM + n0 + bn];
        *(float4*)&Bs[bk][bn] = vb;
        __syncthreads();

        #pragma unroll
        for (int kk = 0; kk < BK; kk++) {
            float4 a0 = *(const float4*)&As[kk][ty * TM];
            float4 a1 = *(const float4*)&As[kk][ty * TM + 4];
            float4 b0 = *(const float4*)&Bs[kk][tx * TN];
            float4 b1 = *(const float4*)&Bs[kk][tx * TN + 4];
            const float ra[TM] = {a0.x, a0.y, a0.z, a0.w, a1.x, a1.y, a1.z, a1.w};
            const float rb[TN] = {b0.x, b0.y, b0.z, b0.w, b1.x, b1.y, b1.z, b1.w};
            #pragma unroll
            for (int i = 0; i < TM; i++)
                #pragma unroll
                for (int j = 0; j < TN; j++)
                    acc[i][j] += ra[i] * rb[j];
        }
        __syncthreads();
    }

    #pragma unroll
    for (int i = 0; i < TM; i++) {
        const int m = m0 + ty * TM + i;   // j index
        #pragma unroll
        for (int j = 0; j < TN; j += 4) {
            float4 v = make_float4(acc[i][j], acc[i][j + 1], acc[i][j + 2], acc[i][j + 3]);
            *(float4*)&outh[((size_t)b * SEQ + m) * DIM + n0 + tx * TN + j] = v;
        }
    }
}

// ---------------------------------------------------------------------------
extern "C" void kernel_launch(void* const* d_in, const int* in_sizes, int n_in,
                              void* d_out, int out_size) {
    const float* P = (const float*)d_in[0];   // premises    [32,1024,1024] f32
    const float* H = (const float*)d_in[1];   // hypothesises[32,1024,1024] f32
    float* out  = (float*)d_out;
    float* outp = out;                                     // attention_p
    float* outh = out + (size_t)BATCH * SEQ * DIM;         // attention_h

    dim3 ggrid(SEQ / BN, SEQ / BM, BATCH);   // (8,8,32)

    gemm_e_kernel<<<ggrid, 256>>>(P, H);
    row_stats_kernel<<<dim3(SEQ / 8, BATCH), 256>>>();
    col_stats_kernel<<<dim3(SEQ / 256, BATCH), 256>>>();
    gemm_p_kernel<<<ggrid, 256>>>(H, outp);
    gemm_h_kernel<<<ggrid, 256>>>(P, outh);
}

// round 10
// speedup vs baseline: 2.1692x; 2.1692x over previous
#include <cuda_runtime.h>
#include <cstdint>
#include <math.h>

#define BATCH 32
#define SEQ   1024
#define DIM   1024
#define BSTRIDE ((size_t)SEQ * DIM)

// ---------------- scratch (__device__ globals) -----------------------------
__device__ float g_E  [(size_t)BATCH * SEQ * SEQ];   // E, then rowsoftmax(E) in-place
__device__ float g_WcT[(size_t)BATCH * SEQ * SEQ];   // colsoftmax(E)^T
__device__ float g_Ht [(size_t)BATCH * SEQ * DIM];
__device__ float g_Pt [(size_t)BATCH * SEQ * DIM];
__device__ float g_rowmax[BATCH * SEQ];
__device__ float g_rowinv[BATCH * SEQ];
__device__ float g_colmax[BATCH * SEQ];
__device__ float g_colinv[BATCH * SEQ];

// ---------------- helpers --------------------------------------------------
__device__ __forceinline__ float cvt_tf32(float x) {
    float r;
    asm("cvt.rna.tf32.f32 %0, %1;" : "=f"(r) : "f"(x));
    return r;
}

__device__ __forceinline__ void mma8(float* c, const uint32_t* a, const uint32_t* b) {
    asm volatile(
        "mma.sync.aligned.m16n8k8.row.col.f32.tf32.tf32.f32 "
        "{%0,%1,%2,%3}, {%4,%5,%6,%7}, {%8,%9}, {%0,%1,%2,%3};"
        : "+f"(c[0]), "+f"(c[1]), "+f"(c[2]), "+f"(c[3])
        : "r"(a[0]), "r"(a[1]), "r"(a[2]), "r"(a[3]), "r"(b[0]), "r"(b[1]));
}

// ---------------- GEMM: C[m,n] = sum_k A[m,k]*B[n,k]  (both K-contiguous) ---
// 128x128 CTA tile, BK=32, 8 warps each 64x32, m16n8k8 tf32 atoms.
// SPLIT: 3-term Dekker-split fp32 emulation (GEMM1). Plain: single tf32 pass.
#define PLANE 4608   // 128 rows * 36 floats (stride 36 = conflict-free frag loads)

template<bool SPLIT>
__global__ void __launch_bounds__(256, SPLIT ? 1 : 2)
gemm_mma(const float* __restrict__ A, const float* __restrict__ B, float* __restrict__ C)
{
    extern __shared__ float sm[];
    constexpr int NPL = SPLIT ? 4 : 2;
    constexpr int STG = NPL * PLANE;

    const int tid = threadIdx.x, lane = tid & 31, wid = tid >> 5;
    const int bz = blockIdx.z;
    const int m0 = blockIdx.y * 128, n0 = blockIdx.x * 128;
    const float* Ab = A + (size_t)bz * BSTRIDE + (size_t)m0 * DIM;
    const float* Bb = B + (size_t)bz * BSTRIDE + (size_t)n0 * DIM;
    const int wm = wid & 1, wn = wid >> 1;
    const int r = lane >> 2, cq = lane & 3;

    float acc[4][4][4] = {};
    float4 ra[4], rb[4];

    auto ldg = [&](int kt) {
        #pragma unroll
        for (int j = 0; j < 4; j++) {
            const int i = tid + j * 256, row = i >> 3, qc = i & 7;
            ra[j] = *(const float4*)(Ab + (size_t)row * DIM + kt * 32 + qc * 4);
            rb[j] = *(const float4*)(Bb + (size_t)row * DIM + kt * 32 + qc * 4);
        }
    };

    auto sts = [&](float* buf) {
        #pragma unroll
        for (int j = 0; j < 4; j++) {
            const int i = tid + j * 256, row = i >> 3, qc = i & 7;
            const int off = row * 36 + qc * 4;
            if (SPLIT) {
                float4 h, l;
                h.x = cvt_tf32(ra[j].x); l.x = cvt_tf32(ra[j].x - h.x);
                h.y = cvt_tf32(ra[j].y); l.y = cvt_tf32(ra[j].y - h.y);
                h.z = cvt_tf32(ra[j].z); l.z = cvt_tf32(ra[j].z - h.z);
                h.w = cvt_tf32(ra[j].w); l.w = cvt_tf32(ra[j].w - h.w);
                *(float4*)(buf + off)         = h;
                *(float4*)(buf + PLANE + off) = l;
                h.x = cvt_tf32(rb[j].x); l.x = cvt_tf32(rb[j].x - h.x);
                h.y = cvt_tf32(rb[j].y); l.y = cvt_tf32(rb[j].y - h.y);
                h.z = cvt_tf32(rb[j].z); l.z = cvt_tf32(rb[j].z - h.z);
                h.w = cvt_tf32(rb[j].w); l.w = cvt_tf32(rb[j].w - h.w);
                *(float4*)(buf + 2 * PLANE + off) = h;
                *(float4*)(buf + 3 * PLANE + off) = l;
            } else {
                float4 h;
                h.x = cvt_tf32(ra[j].x); h.y = cvt_tf32(ra[j].y);
                h.z = cvt_tf32(ra[j].z); h.w = cvt_tf32(ra[j].w);
                *(float4*)(buf + off) = h;
                h.x = cvt_tf32(rb[j].x); h.y = cvt_tf32(rb[j].y);
                h.z = cvt_tf32(rb[j].z); h.w = cvt_tf32(rb[j].w);
                *(float4*)(buf + PLANE + off) = h;
            }
        }
    };

    auto comp = [&](const float* buf) {
        const uint32_t* uAh = (const uint32_t*)buf;
        const uint32_t* uAl = (const uint32_t*)(buf + PLANE);
        const uint32_t* uBh = (const uint32_t*)(buf + (SPLIT ? 2 : 1) * PLANE);
        const uint32_t* uBl = (const uint32_t*)(buf + 3 * PLANE);
        #pragma unroll
        for (int ks = 0; ks < 4; ks++) {
            const int k0 = ks * 8 + cq;
            uint32_t Ah[4][4], Al[4][4];
            #pragma unroll
            for (int ma = 0; ma < 4; ma++) {
                const int rw = (wm * 64 + ma * 16 + r) * 36;
                Ah[ma][0] = uAh[rw + k0];
                Ah[ma][1] = uAh[rw + 8 * 36 + k0];
                Ah[ma][2] = uAh[rw + k0 + 4];
                Ah[ma][3] = uAh[rw + 8 * 36 + k0 + 4];
                if (SPLIT) {
                    Al[ma][0] = uAl[rw + k0];
                    Al[ma][1] = uAl[rw + 8 * 36 + k0];
                    Al[ma][2] = uAl[rw + k0 + 4];
                    Al[ma][3] = uAl[rw + 8 * 36 + k0 + 4];
                }
            }
            #pragma unroll
            for (int na = 0; na < 4; na++) {
                const int cl = (wn * 32 + na * 8 + r) * 36;
                uint32_t Bh[2] = { uBh[cl + k0], uBh[cl + k0 + 4] };
                #pragma unroll
                for (int ma = 0; ma < 4; ma++) mma8(acc[ma][na], Ah[ma], Bh);
                if (SPLIT) {
                    uint32_t Bl[2] = { uBl[cl + k0], uBl[cl + k0 + 4] };
                    #pragma unroll
                    for (int ma = 0; ma < 4; ma++) mma8(acc[ma][na], Al[ma], Bh);
                    #pragma unroll
                    for (int ma = 0; ma < 4; ma++) mma8(acc[ma][na], Ah[ma], Bl);
                }
            }
        }
    };

    if (SPLIT) {
        // prefetch pipeline (regs spare at 1 CTA/SM)
        ldg(0); sts(sm); __syncthreads();
        for (int kt = 0; kt < 32; kt++) {
            if (kt < 31) ldg(kt + 1);
            comp(sm + (kt & 1) * STG);
            if (kt < 31) { sts(sm + ((kt + 1) & 1) * STG); __syncthreads(); }
        }
    } else {
        // low-register variant: ldg after comp; 2 CTAs/SM hide the tile-edge latency
        ldg(0); sts(sm); __syncthreads();
        for (int kt = 0; kt < 32; kt++) {
            comp(sm + (kt & 1) * STG);
            if (kt < 31) { ldg(kt + 1); sts(sm + ((kt + 1) & 1) * STG); __syncthreads(); }
        }
    }

    float* Cb = C + (size_t)bz * BSTRIDE;
    #pragma unroll
    for (int ma = 0; ma < 4; ma++) {
        const int row = m0 + wm * 64 + ma * 16 + r;
        #pragma unroll
        for (int na = 0; na < 4; na++) {
            const int col = n0 + wn * 32 + na * 8 + 2 * cq;
            *(float2*)&Cb[(size_t)row * DIM + col]       = make_float2(acc[ma][na][0], acc[ma][na][1]);
            *(float2*)&Cb[(size_t)(row + 8) * DIM + col] = make_float2(acc[ma][na][2], acc[ma][na][3]);
        }
    }
}

// ---------------- preprocessing / softmax ----------------------------------
__global__ __launch_bounds__(256)
void transpose_kernel(const float* __restrict__ src, float* __restrict__ dst) {
    __shared__ float t[32][33];
    const int b = blockIdx.z;
    const float* s = src + (size_t)b * BSTRIDE;
    float* d = dst + (size_t)b * BSTRIDE;
    const int x = blockIdx.x * 32 + threadIdx.x;
    const int y0 = blockIdx.y * 32;
    #pragma unroll
    for (int r = threadIdx.y; r < 32; r += 8)
        t[r][threadIdx.x] = s[(size_t)(y0 + r) * DIM + x];
    __syncthreads();
    const int x2 = blockIdx.y * 32 + threadIdx.x;
    const int y2 = blockIdx.x * 32;
    #pragma unroll
    for (int r = threadIdx.y; r < 32; r += 8)
        d[(size_t)(y2 + r) * DIM + x2] = t[threadIdx.x][r];
}

__global__ __launch_bounds__(256)
void row_stats_kernel() {
    const int b = blockIdx.y;
    const int warp = threadIdx.x >> 5, lane = threadIdx.x & 31;
    const int row = blockIdx.x * 8 + warp;
    const float* Erow = g_E + (size_t)b * SEQ * SEQ + (size_t)row * SEQ;
    float m = -INFINITY, s = 0.f;
    #pragma unroll 4
    for (int j = lane; j < SEQ; j += 32) {
        float v = Erow[j];
        if (v > m) { s = s * __expf(m - v) + 1.f; m = v; }
        else       { s += __expf(v - m); }
    }
    #pragma unroll
    for (int off = 16; off; off >>= 1) {
        float om = __shfl_down_sync(0xffffffffu, m, off);
        float os = __shfl_down_sync(0xffffffffu, s, off);
        float nm = fmaxf(m, om);
        s = s * __expf(m - nm) + os * __expf(om - nm);
        m = nm;
    }
    if (lane == 0) { g_rowmax[b * SEQ + row] = m; g_rowinv[b * SEQ + row] = 1.f / s; }
}

__global__ __launch_bounds__(256)
void col_stats_kernel() {
    const int b = blockIdx.y;
    const int j = blockIdx.x * 256 + threadIdx.x;
    const float* Eb = g_E + (size_t)b * SEQ * SEQ;
    float m = -INFINITY, s = 0.f;
    #pragma unroll 4
    for (int i = 0; i < SEQ; i++) {
        float v = Eb[(size_t)i * SEQ + j];
        if (v > m) { s = s * __expf(m - v) + 1.f; m = v; }
        else       { s += __expf(v - m); }
    }
    g_colmax[b * SEQ + j] = m;
    g_colinv[b * SEQ + j] = 1.f / s;
}

// WcT[j][i] = exp(E[i][j] - colmax[j]) * colinv[j]
__global__ __launch_bounds__(256)
void wct_kernel() {
    __shared__ float t[32][33];
    const int b = blockIdx.z;
    const float* Eb = g_E + (size_t)b * SEQ * SEQ;
    float* Wb = g_WcT + (size_t)b * SEQ * SEQ;
    const int j = blockIdx.x * 32 + threadIdx.x;
    const int i0 = blockIdx.y * 32;
    const float cm = g_colmax[b * SEQ + j];
    const float ci = g_colinv[b * SEQ + j];
    #pragma unroll
    for (int r = threadIdx.y; r < 32; r += 8)
        t[r][threadIdx.x] = __expf(Eb[(size_t)(i0 + r) * SEQ + j] - cm) * ci;
    __syncthreads();
    const int i2 = blockIdx.y * 32 + threadIdx.x;
    const int j2 = blockIdx.x * 32;
    #pragma unroll
    for (int r = threadIdx.y; r < 32; r += 8)
        Wb[(size_t)(j2 + r) * SEQ + i2] = t[threadIdx.x][r];
}

// E <- rowsoftmax(E) in-place
__global__ __launch_bounds__(256)
void wr_kernel() {
    const int b = blockIdx.y, row = blockIdx.x, t = threadIdx.x;
    const float rm = g_rowmax[b * SEQ + row];
    const float ri = g_rowinv[b * SEQ + row];
    float4* p = (float4*)(g_E + (size_t)b * SEQ * SEQ + (size_t)row * SEQ);
    float4 v = p[t];
    v.x = __expf(v.x - rm) * ri;
    v.y = __expf(v.y - rm) * ri;
    v.z = __expf(v.z - rm) * ri;
    v.w = __expf(v.w - rm) * ri;
    p[t] = v;
}

// ---------------------------------------------------------------------------
extern "C" void kernel_launch(void* const* d_in, const int* in_sizes, int n_in,
                              void* d_out, int out_size) {
    const float* P = (const float*)d_in[0];
    const float* H = (const float*)d_in[1];
    float* outp = (float*)d_out;
    float* outh = (float*)d_out + (size_t)BATCH * SEQ * DIM;

    float* pE;   cudaGetSymbolAddress((void**)&pE,   g_E);
    float* pHt;  cudaGetSymbolAddress((void**)&pHt,  g_Ht);
    float* pPt;  cudaGetSymbolAddress((void**)&pPt,  g_Pt);
    float* pWcT; cudaGetSymbolAddress((void**)&pWcT, g_WcT);

    const int SMEM_SPLIT = 2 * 4 * PLANE * 4;   // 147456
    const int SMEM_PLAIN = 2 * 2 * PLANE * 4;   // 73728
    cudaFuncSetAttribute(gemm_mma<true>,  cudaFuncAttributeMaxDynamicSharedMemorySize, SMEM_SPLIT);
    cudaFuncSetAttribute(gemm_mma<false>, cudaFuncAttributeMaxDynamicSharedMemorySize, SMEM_PLAIN);

    dim3 tgrid(32, 32, BATCH), tblk(32, 8);
    dim3 ggrid(8, 8, BATCH);

    transpose_kernel<<<tgrid, tblk>>>(H, pHt);
    transpose_kernel<<<tgrid, tblk>>>(P, pPt);

    gemm_mma<true><<<ggrid, 256, SMEM_SPLIT>>>(P, H, pE);        // E = P·H^T (fp32-accurate)

    row_stats_kernel<<<dim3(SEQ / 8, BATCH), 256>>>();
    col_stats_kernel<<<dim3(SEQ / 256, BATCH), 256>>>();
    wct_kernel<<<tgrid, tblk>>>();                               // WcT from raw E
    wr_kernel<<<dim3(SEQ, BATCH), 256>>>();                      // E <- rowsoftmax(E)

    gemm_mma<false><<<ggrid, 256, SMEM_PLAIN>>>(pE,   pHt, outp);  // attention_p
    gemm_mma<false><<<ggrid, 256, SMEM_PLAIN>>>(pWcT, pPt, outh);  // attention_h
}